// round 1
// baseline (speedup 1.0000x reference)
#include <cuda_runtime.h>
#include <math.h>

#define Bn 16384
#define Ln 50
#define Dn 128
#define Fn 6
#define CINn 2688
#define H1N 512
#define H2N 256

// ---------------- scratch (static device globals; no runtime allocation) ----
__device__ __align__(16) float g_x  [Bn * Fn * Dn];        // 50 MB  (b,6,128)
__device__ __align__(16) float g_s  [Bn * Fn * Dn];        // 50 MB
__device__ __align__(16) float g_vid[Bn * 5 * Dn];         // 42 MB  (b,5,128)
__device__ __align__(16) float g_c  [Bn * CINn];           // 176 MB (b,2688)
__device__ __align__(16) float g_h1 [Bn * H1N];            // 34 MB
__device__ __align__(16) float g_h2 [Bn * H2N];            // 17 MB

// ---------------- K1: features -> x[b, 6, 128] ------------------------------
__global__ __launch_bounds__(128) void k_features(
    const int* __restrict__ item_id, const float* __restrict__ item_mm,
    const int* __restrict__ likes, const int* __restrict__ views,
    const int* __restrict__ item_seq, const float* __restrict__ item_emb,
    const float* __restrict__ cate_emb, const float* __restrict__ mm_w,
    const float* __restrict__ mm_b, const float* __restrict__ ln_g,
    const float* __restrict__ ln_b)
{
    int b = blockIdx.x, t = threadIdx.x;
    int lane = t & 31, w = t >> 5;
    __shared__ float sm[Dn];
    __shared__ float red[8];

    sm[t] = item_mm[b * Dn + t];
    __syncthreads();

    float y = mm_b[t];
    #pragma unroll 16
    for (int i = 0; i < Dn; i++) y = fmaf(sm[i], mm_w[i * Dn + t], y);

    // LayerNorm over 128
    float s1 = y, s2 = y * y;
    #pragma unroll
    for (int o = 16; o; o >>= 1) {
        s1 += __shfl_xor_sync(0xffffffffu, s1, o);
        s2 += __shfl_xor_sync(0xffffffffu, s2, o);
    }
    if (!lane) { red[w] = s1; red[4 + w] = s2; }
    __syncthreads();
    float mu = (red[0] + red[1] + red[2] + red[3]) * (1.f / Dn);
    float m2 = (red[4] + red[5] + red[6] + red[7]) * (1.f / Dn);
    float var = m2 - mu * mu;
    float yn = (y - mu) * rsqrtf(var + 1e-5f) * ln_g[t] + ln_b[t];
    float img = 0.5f * yn * (1.f + erff(yn * 0.70710678118654752f));

    // masked mean over sequence
    float hs = 0.f, cnt = 0.f;
    const int* seq = item_seq + b * Ln;
    for (int l = 0; l < Ln; l++) {
        int id = seq[l];
        if (id != 0) { hs += item_emb[(size_t)id * Dn + t]; cnt += 1.f; }
    }
    float hist = hs / fmaxf(cnt, 1.f);

    float* xb = g_x + (size_t)b * (Fn * Dn);
    xb[0 * Dn + t] = 0.f;
    xb[1 * Dn + t] = cate_emb[likes[b] * Dn + t];
    xb[2 * Dn + t] = cate_emb[views[b] * Dn + t];
    xb[3 * Dn + t] = item_emb[(size_t)item_id[b] * Dn + t];
    xb[4 * Dn + t] = img;
    xb[5 * Dn + t] = hist;
}

// ---------------- K2: GAT + SE -> c[:, :768] and s ---------------------------
__global__ __launch_bounds__(128) void k_gnn(
    const float* __restrict__ gnn_W, const float* __restrict__ gnn_a,
    const float* __restrict__ se_w1, const float* __restrict__ se_b1,
    const float* __restrict__ se_w2, const float* __restrict__ se_b2)
{
    int b = blockIdx.x, t = threadIdx.x;
    int h = t >> 5, lane = t & 31;
    __shared__ float xs[Fn * Dn];
    __shared__ float red[4 * Fn];

    const float* xb = g_x + (size_t)b * Fn * Dn;
    #pragma unroll
    for (int n = 0; n < Fn; n++) xs[n * Dn + t] = xb[n * Dn + t];
    __syncthreads();

    // hp[b,n,h,o] = sum_i x[b,n,i] * W[h,i,o];  thread = (h, o=lane)
    float hp[Fn];
    const float* Wh = gnn_W + h * (Dn * 32);
    #pragma unroll
    for (int n = 0; n < Fn; n++) {
        float acc = 0.f;
        #pragma unroll 8
        for (int i = 0; i < Dn; i++) acc = fmaf(xs[n * Dn + i], Wh[i * 32 + lane], acc);
        hp[n] = acc;
    }

    float a1 = gnn_a[h * 64 + lane];
    float a2 = gnn_a[h * 64 + 32 + lane];
    float ei[Fn], ej[Fn];
    #pragma unroll
    for (int n = 0; n < Fn; n++) {
        float v1 = hp[n] * a1, v2 = hp[n] * a2;
        #pragma unroll
        for (int o = 16; o; o >>= 1) {
            v1 += __shfl_xor_sync(0xffffffffu, v1, o);
            v2 += __shfl_xor_sync(0xffffffffu, v2, o);
        }
        ei[n] = v1; ej[n] = v2;
    }

    float gnn[Fn];
    #pragma unroll
    for (int n = 0; n < Fn; n++) {
        float em[Fn], mx = -1e30f;
        #pragma unroll
        for (int m = 0; m < Fn; m++) {
            float e = ei[n] + ej[m];
            e = e > 0.f ? e : 0.2f * e;       // leaky relu
            em[m] = e; mx = fmaxf(mx, e);
        }
        float ss = 0.f;
        #pragma unroll
        for (int m = 0; m < Fn; m++) { em[m] = expf(em[m] - mx); ss += em[m]; }
        float inv = 1.f / ss, acc = 0.f;
        #pragma unroll
        for (int m = 0; m < Fn; m++) acc = fmaf(em[m], hp[m], acc);
        float hn = acc * inv + xs[n * Dn + t];
        gnn[n] = hn > 0.f ? hn : expm1f(hn);  // elu
    }

    // SE: z[n] = mean_d gnn[n][d]
    #pragma unroll
    for (int n = 0; n < Fn; n++) {
        float v = gnn[n];
        #pragma unroll
        for (int o = 16; o; o >>= 1) v += __shfl_xor_sync(0xffffffffu, v, o);
        if (!lane) red[h * Fn + n] = v;
    }
    __syncthreads();

    float wv[Fn];
    {
        float z[Fn];
        #pragma unroll
        for (int n = 0; n < Fn; n++)
            z[n] = (red[0 * Fn + n] + red[1 * Fn + n] + red[2 * Fn + n] + red[3 * Fn + n]) * (1.f / Dn);
        float a[3];
        #pragma unroll
        for (int k = 0; k < 3; k++) {
            float v = se_b1[k];
            #pragma unroll
            for (int n = 0; n < Fn; n++) v = fmaf(z[n], se_w1[n * 3 + k], v);
            a[k] = fmaxf(v, 0.f);
        }
        #pragma unroll
        for (int f = 0; f < Fn; f++) {
            float v = se_b2[f];
            #pragma unroll
            for (int k = 0; k < 3; k++) v = fmaf(a[k], se_w2[k * 6 + f], v);
            wv[f] = 1.f / (1.f + expf(-v));
        }
    }

    float* cb = g_c + (size_t)b * CINn;
    float* sb = g_s + (size_t)b * Fn * Dn;
    #pragma unroll
    for (int n = 0; n < Fn; n++) {
        cb[n * Dn + t] = gnn[n];
        sb[n * Dn + t] = gnn[n] * wv[n];
    }
}

// ---------------- generic register-blocked SGEMM ----------------------------
// C[M,N] = A[M,K] @ W[K,N] (+ optional bias/bn/gelu epilogue)
// BM=128, BN=64, BK=16, 256 threads, 8x4 per-thread tile.
#define BMg 128
#define BNg 64
#define BKg 16

__global__ __launch_bounds__(256) void k_gemm(
    const float* __restrict__ A, int lda, long saz,
    const float* __restrict__ Wt, int ldb, long swz,
    float* __restrict__ Co, int ldc, long scz,
    int K,
    const float* __restrict__ bias, const float* __restrict__ bng,
    const float* __restrict__ bnb, int mode)
{
    A  += (size_t)blockIdx.z * saz;
    Wt += (size_t)blockIdx.z * swz;
    Co += (size_t)blockIdx.z * scz;
    int bm = blockIdx.y * BMg, bn = blockIdx.x * BNg;
    int tid = threadIdx.x;
    int tx = tid & 15, ty = tid >> 4;

    __shared__ float As[BKg][BMg + 4];
    __shared__ float Bs[BKg][BNg + 4];

    float acc[8][4];
    #pragma unroll
    for (int i = 0; i < 8; i++)
        #pragma unroll
        for (int j = 0; j < 4; j++) acc[i][j] = 0.f;

    for (int k0 = 0; k0 < K; k0 += BKg) {
        #pragma unroll
        for (int ii = 0; ii < 2; ii++) {
            int e = tid + ii * 256;
            int m = e >> 2, k4 = (e & 3) * 4;
            const float4 v = *reinterpret_cast<const float4*>(&A[(size_t)(bm + m) * lda + k0 + k4]);
            As[k4 + 0][m] = v.x; As[k4 + 1][m] = v.y;
            As[k4 + 2][m] = v.z; As[k4 + 3][m] = v.w;
        }
        {
            int kk = tid >> 4, c4 = (tid & 15) * 4;
            const float4 v = *reinterpret_cast<const float4*>(&Wt[(size_t)(k0 + kk) * ldb + bn + c4]);
            Bs[kk][c4 + 0] = v.x; Bs[kk][c4 + 1] = v.y;
            Bs[kk][c4 + 2] = v.z; Bs[kk][c4 + 3] = v.w;
        }
        __syncthreads();
        #pragma unroll
        for (int kk = 0; kk < BKg; kk++) {
            float a[8], bb4[4];
            #pragma unroll
            for (int i = 0; i < 8; i++) a[i] = As[kk][ty * 8 + i];
            #pragma unroll
            for (int j = 0; j < 4; j++) bb4[j] = Bs[kk][tx * 4 + j];
            #pragma unroll
            for (int i = 0; i < 8; i++)
                #pragma unroll
                for (int j = 0; j < 4; j++) acc[i][j] = fmaf(a[i], bb4[j], acc[i][j]);
        }
        __syncthreads();
    }

    const float bnscale = 0.999995000037499688f;  // 1/sqrt(1+1e-5)
    #pragma unroll
    for (int i = 0; i < 8; i++) {
        int row = bm + ty * 8 + i;
        #pragma unroll
        for (int j = 0; j < 4; j++) {
            int col = bn + tx * 4 + j;
            float v = acc[i][j];
            if (mode == 1) {
                v += bias[col];
                v = v * (bng[col] * bnscale) + bnb[col];
                v = 0.5f * v * (1.f + erff(v * 0.70710678118654752f));
            }
            Co[(size_t)row * ldc + col] = v;
        }
    }
}

// ---------------- K4: bilinear pairs -> c[:, 768:] ---------------------------
__global__ __launch_bounds__(128) void k_pairs()
{
    int b = blockIdx.x, t = threadIdx.x;
    const float* vid = g_vid + (size_t)b * (5 * Dn);
    const float* sb  = g_s   + (size_t)b * (Fn * Dn);
    float* cp = g_c + (size_t)b * CINn + Fn * Dn;
    int p = 0;
    #pragma unroll
    for (int i = 0; i < 5; i++) {
        float vi = vid[i * Dn + t];
        #pragma unroll
        for (int j = i + 1; j < 6; j++) {
            cp[p * Dn + t] = vi * sb[j * Dn + t];
            p++;
        }
    }
}

// ---------------- K5: final dot + sigmoid ------------------------------------
__global__ __launch_bounds__(256) void k_final(
    const float* __restrict__ w3, const float* __restrict__ b3,
    float* __restrict__ out)
{
    int warp = threadIdx.x >> 5, lane = threadIdx.x & 31;
    int b = blockIdx.x * 8 + warp;
    const float* hh = g_h2 + (size_t)b * H2N;
    float acc = 0.f;
    #pragma unroll
    for (int i = 0; i < 8; i++) acc = fmaf(hh[lane + i * 32], w3[lane + i * 32], acc);
    #pragma unroll
    for (int o = 16; o; o >>= 1) acc += __shfl_xor_sync(0xffffffffu, acc, o);
    if (!lane) out[b] = 1.f / (1.f + expf(-(acc + b3[0])));
}

// ---------------- launch -----------------------------------------------------
extern "C" void kernel_launch(void* const* d_in, const int* in_sizes, int n_in,
                              void* d_out, int out_size)
{
    const int*   item_id  = (const int*)  d_in[0];
    const float* item_mm  = (const float*)d_in[1];
    const int*   likes    = (const int*)  d_in[2];
    const int*   views    = (const int*)  d_in[3];
    const int*   item_seq = (const int*)  d_in[4];
    const float* item_emb = (const float*)d_in[5];
    const float* cate_emb = (const float*)d_in[6];
    const float* mm_w     = (const float*)d_in[7];
    const float* mm_b     = (const float*)d_in[8];
    const float* ln_g     = (const float*)d_in[9];
    const float* ln_b     = (const float*)d_in[10];
    const float* gnn_W    = (const float*)d_in[11];
    const float* gnn_a    = (const float*)d_in[12];
    const float* se_w1    = (const float*)d_in[13];
    const float* se_b1    = (const float*)d_in[14];
    const float* se_w2    = (const float*)d_in[15];
    const float* se_b2    = (const float*)d_in[16];
    const float* bi_W     = (const float*)d_in[17];
    const float* w1       = (const float*)d_in[18];
    const float* b1       = (const float*)d_in[19];
    const float* bn1g     = (const float*)d_in[20];
    const float* bn1b     = (const float*)d_in[21];
    const float* w2       = (const float*)d_in[22];
    const float* b2       = (const float*)d_in[23];
    const float* bn2g     = (const float*)d_in[24];
    const float* bn2b     = (const float*)d_in[25];
    const float* w3       = (const float*)d_in[26];
    const float* b3       = (const float*)d_in[27];
    float* out = (float*)d_out;

    float *ps, *pv, *pc, *ph1, *ph2;
    cudaGetSymbolAddress((void**)&ps,  g_s);
    cudaGetSymbolAddress((void**)&pv,  g_vid);
    cudaGetSymbolAddress((void**)&pc,  g_c);
    cudaGetSymbolAddress((void**)&ph1, g_h1);
    cudaGetSymbolAddress((void**)&ph2, g_h2);

    k_features<<<Bn, 128>>>(item_id, item_mm, likes, views, item_seq,
                            item_emb, cate_emb, mm_w, mm_b, ln_g, ln_b);
    k_gnn<<<Bn, 128>>>(gnn_W, gnn_a, se_w1, se_b1, se_w2, se_b2);

    // bilinear: 5 fields as grid.z; vid[b,f,:] = s[b,f,:] @ bi_W[f]
    {
        dim3 grid(128 / BNg, Bn / BMg, 5);
        k_gemm<<<grid, 256>>>(ps, Fn * Dn, Dn,
                              bi_W, Dn, (long)Dn * Dn,
                              pv, 5 * Dn, Dn,
                              Dn, nullptr, nullptr, nullptr, 0);
    }
    k_pairs<<<Bn, 128>>>();

    // layer 1: c[B,2688] @ w1[2688,512], bn+gelu
    {
        dim3 grid(H1N / BNg, Bn / BMg, 1);
        k_gemm<<<grid, 256>>>(pc, CINn, 0, w1, H1N, 0, ph1, H1N, 0,
                              CINn, b1, bn1g, bn1b, 1);
    }
    // layer 2: h1[B,512] @ w2[512,256], bn+gelu
    {
        dim3 grid(H2N / BNg, Bn / BMg, 1);
        k_gemm<<<grid, 256>>>(ph1, H1N, 0, w2, H2N, 0, ph2, H2N, 0,
                              H1N, b2, bn2g, bn2b, 1);
    }
    k_final<<<Bn / 8, 256>>>(w3, b3, out);
}

// round 3
// speedup vs baseline: 1.4660x; 1.4660x over previous
#include <cuda_runtime.h>
#include <cuda_bf16.h>
#include <math.h>
#include <stdint.h>

#define Bn 16384
#define Ln 50
#define Dn 128
#define Fn 6
#define CINn 2688
#define H1N 512
#define H2N 256

// ---------------- scratch (static device globals) ---------------------------
__device__ __align__(16) float g_x  [Bn * Fn * Dn];
__device__ __align__(16) float g_s  [Bn * Fn * Dn];
__device__ __align__(16) float g_vid[Bn * 5 * Dn];
__device__ __align__(16) __nv_bfloat16 g_c_hi[Bn * CINn];
__device__ __align__(16) __nv_bfloat16 g_c_lo[Bn * CINn];
__device__ __align__(16) __nv_bfloat16 g_h1_hi[Bn * H1N];
__device__ __align__(16) __nv_bfloat16 g_h1_lo[Bn * H1N];
__device__ __align__(16) float g_h2 [Bn * H2N];
__device__ __align__(16) __nv_bfloat16 g_w1t_hi[H1N * CINn];
__device__ __align__(16) __nv_bfloat16 g_w1t_lo[H1N * CINn];
__device__ __align__(16) __nv_bfloat16 g_w2t_hi[H2N * H1N];
__device__ __align__(16) __nv_bfloat16 g_w2t_lo[H2N * H1N];

// ---------------- PTX helpers (sm_80-level only; no 'a'-suffix features) -----
__device__ __forceinline__ uint32_t smem_u32(const void* p) {
    uint32_t a;
    asm("{ .reg .u64 t; cvta.to.shared.u64 t, %1; cvt.u32.u64 %0, t; }" : "=r"(a) : "l"(p));
    return a;
}
__device__ __forceinline__ void cp16(uint32_t dst, const void* src) {
    asm volatile("cp.async.cg.shared.global [%0], [%1], 16;" :: "r"(dst), "l"(src));
}
__device__ __forceinline__ void cp_commit() {
    asm volatile("cp.async.commit_group;" ::: "memory");
}
template <int N>
__device__ __forceinline__ void cp_wait() {
    asm volatile("cp.async.wait_group %0;" :: "n"(N) : "memory");
}
__device__ __forceinline__ void ldsm4(uint32_t* r, uint32_t addr) {
    asm volatile("ldmatrix.sync.aligned.m8n8.x4.shared.b16 {%0,%1,%2,%3}, [%4];"
                 : "=r"(r[0]), "=r"(r[1]), "=r"(r[2]), "=r"(r[3]) : "r"(addr));
}
__device__ __forceinline__ void mma_bf16(float* d, const uint32_t* a, const uint32_t* b) {
    asm volatile(
        "mma.sync.aligned.m16n8k16.row.col.f32.bf16.bf16.f32 "
        "{%0,%1,%2,%3}, {%4,%5,%6,%7}, {%8,%9}, {%0,%1,%2,%3};"
        : "+f"(d[0]), "+f"(d[1]), "+f"(d[2]), "+f"(d[3])
        : "r"(a[0]), "r"(a[1]), "r"(a[2]), "r"(a[3]), "r"(b[0]), "r"(b[1]));
}

// ---------------- K1: features -> x[b, 6, 128] ------------------------------
__global__ __launch_bounds__(128) void k_features(
    const int* __restrict__ item_id, const float* __restrict__ item_mm,
    const int* __restrict__ likes, const int* __restrict__ views,
    const int* __restrict__ item_seq, const float* __restrict__ item_emb,
    const float* __restrict__ cate_emb, const float* __restrict__ mm_w,
    const float* __restrict__ mm_b, const float* __restrict__ ln_g,
    const float* __restrict__ ln_b)
{
    int b = blockIdx.x, t = threadIdx.x;
    int lane = t & 31, w = t >> 5;
    __shared__ float sm[Dn];
    __shared__ float red[8];

    sm[t] = item_mm[b * Dn + t];
    __syncthreads();

    float y = mm_b[t];
    #pragma unroll 16
    for (int i = 0; i < Dn; i++) y = fmaf(sm[i], mm_w[i * Dn + t], y);

    float s1 = y, s2 = y * y;
    #pragma unroll
    for (int o = 16; o; o >>= 1) {
        s1 += __shfl_xor_sync(0xffffffffu, s1, o);
        s2 += __shfl_xor_sync(0xffffffffu, s2, o);
    }
    if (!lane) { red[w] = s1; red[4 + w] = s2; }
    __syncthreads();
    float mu = (red[0] + red[1] + red[2] + red[3]) * (1.f / Dn);
    float m2 = (red[4] + red[5] + red[6] + red[7]) * (1.f / Dn);
    float var = m2 - mu * mu;
    float yn = (y - mu) * rsqrtf(var + 1e-5f) * ln_g[t] + ln_b[t];
    float img = 0.5f * yn * (1.f + erff(yn * 0.70710678118654752f));

    float hs = 0.f, cnt = 0.f;
    const int* seq = item_seq + b * Ln;
    for (int l = 0; l < Ln; l++) {
        int id = seq[l];
        if (id != 0) { hs += item_emb[(size_t)id * Dn + t]; cnt += 1.f; }
    }
    float hist = hs / fmaxf(cnt, 1.f);

    float* xb = g_x + (size_t)b * (Fn * Dn);
    xb[0 * Dn + t] = 0.f;
    xb[1 * Dn + t] = cate_emb[likes[b] * Dn + t];
    xb[2 * Dn + t] = cate_emb[views[b] * Dn + t];
    xb[3 * Dn + t] = item_emb[(size_t)item_id[b] * Dn + t];
    xb[4 * Dn + t] = img;
    xb[5 * Dn + t] = hist;
}

// ---------------- K2: GAT + SE -> c_hi/c_lo[:, :768] and s -------------------
__global__ __launch_bounds__(128) void k_gnn(
    const float* __restrict__ gnn_W, const float* __restrict__ gnn_a,
    const float* __restrict__ se_w1, const float* __restrict__ se_b1,
    const float* __restrict__ se_w2, const float* __restrict__ se_b2)
{
    int b = blockIdx.x, t = threadIdx.x;
    int h = t >> 5, lane = t & 31;
    __shared__ float xs[Fn * Dn];
    __shared__ float red[4 * Fn];

    const float* xb = g_x + (size_t)b * Fn * Dn;
    #pragma unroll
    for (int n = 0; n < Fn; n++) xs[n * Dn + t] = xb[n * Dn + t];
    __syncthreads();

    float hp[Fn];
    const float* Wh = gnn_W + h * (Dn * 32);
    #pragma unroll
    for (int n = 0; n < Fn; n++) {
        float acc = 0.f;
        #pragma unroll 8
        for (int i = 0; i < Dn; i++) acc = fmaf(xs[n * Dn + i], Wh[i * 32 + lane], acc);
        hp[n] = acc;
    }

    float a1 = gnn_a[h * 64 + lane];
    float a2 = gnn_a[h * 64 + 32 + lane];
    float ei[Fn], ej[Fn];
    #pragma unroll
    for (int n = 0; n < Fn; n++) {
        float v1 = hp[n] * a1, v2 = hp[n] * a2;
        #pragma unroll
        for (int o = 16; o; o >>= 1) {
            v1 += __shfl_xor_sync(0xffffffffu, v1, o);
            v2 += __shfl_xor_sync(0xffffffffu, v2, o);
        }
        ei[n] = v1; ej[n] = v2;
    }

    float gnn[Fn];
    #pragma unroll
    for (int n = 0; n < Fn; n++) {
        float em[Fn], mx = -1e30f;
        #pragma unroll
        for (int m = 0; m < Fn; m++) {
            float e = ei[n] + ej[m];
            e = e > 0.f ? e : 0.2f * e;
            em[m] = e; mx = fmaxf(mx, e);
        }
        float ss = 0.f;
        #pragma unroll
        for (int m = 0; m < Fn; m++) { em[m] = expf(em[m] - mx); ss += em[m]; }
        float inv = 1.f / ss, acc = 0.f;
        #pragma unroll
        for (int m = 0; m < Fn; m++) acc = fmaf(em[m], hp[m], acc);
        float hn = acc * inv + xs[n * Dn + t];
        gnn[n] = hn > 0.f ? hn : expm1f(hn);
    }

    #pragma unroll
    for (int n = 0; n < Fn; n++) {
        float v = gnn[n];
        #pragma unroll
        for (int o = 16; o; o >>= 1) v += __shfl_xor_sync(0xffffffffu, v, o);
        if (!lane) red[h * Fn + n] = v;
    }
    __syncthreads();

    float wv[Fn];
    {
        float z[Fn];
        #pragma unroll
        for (int n = 0; n < Fn; n++)
            z[n] = (red[0 * Fn + n] + red[1 * Fn + n] + red[2 * Fn + n] + red[3 * Fn + n]) * (1.f / Dn);
        float a[3];
        #pragma unroll
        for (int k = 0; k < 3; k++) {
            float v = se_b1[k];
            #pragma unroll
            for (int n = 0; n < Fn; n++) v = fmaf(z[n], se_w1[n * 3 + k], v);
            a[k] = fmaxf(v, 0.f);
        }
        #pragma unroll
        for (int f = 0; f < Fn; f++) {
            float v = se_b2[f];
            #pragma unroll
            for (int k = 0; k < 3; k++) v = fmaf(a[k], se_w2[k * 6 + f], v);
            wv[f] = 1.f / (1.f + expf(-v));
        }
    }

    __nv_bfloat16* ch = g_c_hi + (size_t)b * CINn;
    __nv_bfloat16* cl = g_c_lo + (size_t)b * CINn;
    float* sb = g_s + (size_t)b * Fn * Dn;
    #pragma unroll
    for (int n = 0; n < Fn; n++) {
        float v = gnn[n];
        __nv_bfloat16 hi = __float2bfloat16(v);
        ch[n * Dn + t] = hi;
        cl[n * Dn + t] = __float2bfloat16(v - __bfloat162float(hi));
        sb[n * Dn + t] = v * wv[n];
    }
}

// ---------------- fp32 SGEMM for the bilinear (small) ------------------------
#define BMg 128
#define BNg 64
#define BKg 16
__global__ __launch_bounds__(256) void k_gemm(
    const float* __restrict__ A, int lda, long saz,
    const float* __restrict__ Wt, int ldb, long swz,
    float* __restrict__ Co, int ldc, long scz, int K)
{
    A  += (size_t)blockIdx.z * saz;
    Wt += (size_t)blockIdx.z * swz;
    Co += (size_t)blockIdx.z * scz;
    int bm = blockIdx.y * BMg, bn = blockIdx.x * BNg;
    int tid = threadIdx.x;
    int tx = tid & 15, ty = tid >> 4;

    __shared__ float As[BKg][BMg + 4];
    __shared__ float Bs[BKg][BNg + 4];

    float acc[8][4];
    #pragma unroll
    for (int i = 0; i < 8; i++)
        #pragma unroll
        for (int j = 0; j < 4; j++) acc[i][j] = 0.f;

    for (int k0 = 0; k0 < K; k0 += BKg) {
        #pragma unroll
        for (int ii = 0; ii < 2; ii++) {
            int e = tid + ii * 256;
            int m = e >> 2, k4 = (e & 3) * 4;
            const float4 v = *reinterpret_cast<const float4*>(&A[(size_t)(bm + m) * lda + k0 + k4]);
            As[k4 + 0][m] = v.x; As[k4 + 1][m] = v.y;
            As[k4 + 2][m] = v.z; As[k4 + 3][m] = v.w;
        }
        {
            int kk = tid >> 4, c4 = (tid & 15) * 4;
            const float4 v = *reinterpret_cast<const float4*>(&Wt[(size_t)(k0 + kk) * ldb + bn + c4]);
            Bs[kk][c4 + 0] = v.x; Bs[kk][c4 + 1] = v.y;
            Bs[kk][c4 + 2] = v.z; Bs[kk][c4 + 3] = v.w;
        }
        __syncthreads();
        #pragma unroll
        for (int kk = 0; kk < BKg; kk++) {
            float a[8], bb4[4];
            #pragma unroll
            for (int i = 0; i < 8; i++) a[i] = As[kk][ty * 8 + i];
            #pragma unroll
            for (int j = 0; j < 4; j++) bb4[j] = Bs[kk][tx * 4 + j];
            #pragma unroll
            for (int i = 0; i < 8; i++)
                #pragma unroll
                for (int j = 0; j < 4; j++) acc[i][j] = fmaf(a[i], bb4[j], acc[i][j]);
        }
        __syncthreads();
    }
    #pragma unroll
    for (int i = 0; i < 8; i++) {
        int row = bm + ty * 8 + i;
        #pragma unroll
        for (int j = 0; j < 4; j++)
            Co[(size_t)row * ldc + bn + tx * 4 + j] = acc[i][j];
    }
}

// ---------------- K4: bilinear pairs -> c_hi/c_lo[:, 768:] -------------------
__global__ __launch_bounds__(128) void k_pairs()
{
    int b = blockIdx.x, t = threadIdx.x;
    const float* vid = g_vid + (size_t)b * (5 * Dn);
    const float* sb  = g_s   + (size_t)b * (Fn * Dn);
    __nv_bfloat16* ch = g_c_hi + (size_t)b * CINn + Fn * Dn;
    __nv_bfloat16* cl = g_c_lo + (size_t)b * CINn + Fn * Dn;
    int p = 0;
    #pragma unroll
    for (int i = 0; i < 5; i++) {
        float vi = vid[i * Dn + t];
        #pragma unroll
        for (int j = i + 1; j < 6; j++) {
            float v = vi * sb[j * Dn + t];
            __nv_bfloat16 hi = __float2bfloat16(v);
            ch[p * Dn + t] = hi;
            cl[p * Dn + t] = __float2bfloat16(v - __bfloat162float(hi));
            p++;
        }
    }
}

// ---------------- weight transpose + bf16 split ------------------------------
__global__ __launch_bounds__(256) void k_wsplit(
    const float* __restrict__ W, __nv_bfloat16* __restrict__ Th,
    __nv_bfloat16* __restrict__ Tl, int K, int N)
{
    int idx = blockIdx.x * 256 + threadIdx.x;
    if (idx >= K * N) return;
    int k = idx / N, n = idx - k * N;
    float v = W[idx];
    __nv_bfloat16 hi = __float2bfloat16(v);
    Th[(size_t)n * K + k] = hi;
    Tl[(size_t)n * K + k] = __float2bfloat16(v - __bfloat162float(hi));
}

// ---------------- bf16-split GEMM via mma.sync (HMMA) + fused epilogue -------
// D[M,N] = A[M,K] @ B[N,K]^T, A/B = hi+lo bf16 (3 mma terms per K-step).
// CTA tile 128x128, BK=32, 256 threads, warps 2(M) x 4(N), warp tile 64x32.
#define BM 128
#define BN 128
#define BK 32
#define ROWB 80u                 // padded row pitch in bytes (64B data + 16B pad)
#define OFF_AH 0u
#define OFF_AL 10240u
#define OFF_BH 20480u
#define OFF_BL 30720u
#define STAGEB 40960u
#define SMEM_MMA (2 * STAGEB)

__global__ __launch_bounds__(256, 1) void k_mma(
    const __nv_bfloat16* __restrict__ Ah, const __nv_bfloat16* __restrict__ Al,
    const __nv_bfloat16* __restrict__ Bh, const __nv_bfloat16* __restrict__ Bl,
    int K,
    float* __restrict__ outf, __nv_bfloat16* __restrict__ oh,
    __nv_bfloat16* __restrict__ ol, int ldc,
    const float* __restrict__ bias, const float* __restrict__ bng,
    const float* __restrict__ bnb, int mode)
{
    extern __shared__ char smem[];
    const uint32_t sbase = smem_u32(smem);
    const int tid = threadIdx.x;
    const int lane = tid & 31, wid = tid >> 5;
    const int wm = wid >> 2, wn = wid & 3;       // 2 x 4 warps
    const int bm = blockIdx.y * BM, bn = blockIdx.x * BN;

    float acc[4][4][4];
    #pragma unroll
    for (int mi = 0; mi < 4; mi++)
        #pragma unroll
        for (int ni = 0; ni < 4; ni++)
            #pragma unroll
            for (int q = 0; q < 4; q++) acc[mi][ni][q] = 0.f;

    // per-thread ldmatrix byte offsets (within a stage)
    const uint32_t a_base = (uint32_t)(wm * 64 + (lane & 15)) * ROWB + (uint32_t)((lane >> 4) * 16);
    const uint32_t b_base = (uint32_t)(wn * 32 + (lane & 7) + ((lane >> 4) << 3)) * ROWB
                          + (uint32_t)(((lane >> 3) & 1) * 16);

    const int nIter = K / BK;

    // stage loader: 8 cp.async per thread (2 chunks x {Ah,Al,Bh,Bl})
    auto load_stage = [&](int buf, int k0) {
        uint32_t base = sbase + (uint32_t)buf * STAGEB;
        #pragma unroll
        for (int half = 0; half < 2; half++) {
            int e = tid + half * 256;
            int r = e >> 2, c = e & 3;
            uint32_t off = (uint32_t)r * ROWB + (uint32_t)c * 16;
            size_t sa = (size_t)(bm + r) * K + k0 + c * 8;
            size_t sbv = (size_t)(bn + r) * K + k0 + c * 8;
            cp16(base + OFF_AH + off, Ah + sa);
            cp16(base + OFF_AL + off, Al + sa);
            cp16(base + OFF_BH + off, Bh + sbv);
            cp16(base + OFF_BL + off, Bl + sbv);
        }
    };

    load_stage(0, 0);
    cp_commit();

    for (int it = 0; it < nIter; it++) {
        if (it + 1 < nIter) {
            load_stage((it + 1) & 1, (it + 1) * BK);
            cp_commit();
            cp_wait<1>();
        } else {
            cp_wait<0>();
        }
        __syncthreads();

        uint32_t base = sbase + (uint32_t)(it & 1) * STAGEB;
        #pragma unroll
        for (int ks = 0; ks < 2; ks++) {
            uint32_t koff = (uint32_t)ks * 32;
            uint32_t ah[4][4], al[4][4], bh[2][4], bl[2][4];
            #pragma unroll
            for (int mi = 0; mi < 4; mi++) {
                uint32_t ao = a_base + (uint32_t)mi * 16 * ROWB + koff;
                ldsm4(ah[mi], base + OFF_AH + ao);
                ldsm4(al[mi], base + OFF_AL + ao);
            }
            #pragma unroll
            for (int nq = 0; nq < 2; nq++) {
                uint32_t bo = b_base + (uint32_t)nq * 16 * ROWB + koff;
                ldsm4(bh[nq], base + OFF_BH + bo);
                ldsm4(bl[nq], base + OFF_BL + bo);
            }
            #pragma unroll
            for (int mi = 0; mi < 4; mi++) {
                #pragma unroll
                for (int ni = 0; ni < 4; ni++) {
                    const uint32_t* bhp = &bh[ni >> 1][(ni & 1) * 2];
                    const uint32_t* blp = &bl[ni >> 1][(ni & 1) * 2];
                    mma_bf16(acc[mi][ni], ah[mi], bhp);
                    mma_bf16(acc[mi][ni], ah[mi], blp);
                    mma_bf16(acc[mi][ni], al[mi], bhp);
                }
            }
        }
        __syncthreads();
    }

    // epilogue: bias + bn + gelu, write
    const float bnscale = 0.999995000037499688f;  // 1/sqrt(1+1e-5)
    #pragma unroll
    for (int ni = 0; ni < 4; ni++) {
        int col = bn + wn * 32 + ni * 8 + (lane & 3) * 2;
        float bi0 = bias[col],     bi1 = bias[col + 1];
        float g0 = bng[col] * bnscale, g1 = bng[col + 1] * bnscale;
        float bb0 = bnb[col],      bb1 = bnb[col + 1];
        #pragma unroll
        for (int mi = 0; mi < 4; mi++) {
            int r0 = bm + wm * 64 + mi * 16 + (lane >> 2);
            #pragma unroll
            for (int half = 0; half < 2; half++) {
                int row = r0 + half * 8;
                float v0 = acc[mi][ni][half * 2 + 0];
                float v1 = acc[mi][ni][half * 2 + 1];
                v0 = (v0 + bi0) * g0 + bb0;
                v1 = (v1 + bi1) * g1 + bb1;
                v0 = 0.5f * v0 * (1.f + erff(v0 * 0.70710678118654752f));
                v1 = 0.5f * v1 * (1.f + erff(v1 * 0.70710678118654752f));
                if (mode == 2) {
                    outf[(size_t)row * ldc + col]     = v0;
                    outf[(size_t)row * ldc + col + 1] = v1;
                } else {
                    __nv_bfloat16 h0 = __float2bfloat16(v0);
                    __nv_bfloat16 h1 = __float2bfloat16(v1);
                    oh[(size_t)row * ldc + col]     = h0;
                    oh[(size_t)row * ldc + col + 1] = h1;
                    ol[(size_t)row * ldc + col]     = __float2bfloat16(v0 - __bfloat162float(h0));
                    ol[(size_t)row * ldc + col + 1] = __float2bfloat16(v1 - __bfloat162float(h1));
                }
            }
        }
    }
}

// ---------------- K5: final dot + sigmoid ------------------------------------
__global__ __launch_bounds__(256) void k_final(
    const float* __restrict__ w3, const float* __restrict__ b3,
    float* __restrict__ out)
{
    int warp = threadIdx.x >> 5, lane = threadIdx.x & 31;
    int b = blockIdx.x * 8 + warp;
    const float* hh = g_h2 + (size_t)b * H2N;
    float acc = 0.f;
    #pragma unroll
    for (int i = 0; i < 8; i++) acc = fmaf(hh[lane + i * 32], w3[lane + i * 32], acc);
    #pragma unroll
    for (int o = 16; o; o >>= 1) acc += __shfl_xor_sync(0xffffffffu, acc, o);
    if (!lane) out[b] = 1.f / (1.f + expf(-(acc + b3[0])));
}

// ---------------- launch -----------------------------------------------------
extern "C" void kernel_launch(void* const* d_in, const int* in_sizes, int n_in,
                              void* d_out, int out_size)
{
    const int*   item_id  = (const int*)  d_in[0];
    const float* item_mm  = (const float*)d_in[1];
    const int*   likes    = (const int*)  d_in[2];
    const int*   views    = (const int*)  d_in[3];
    const int*   item_seq = (const int*)  d_in[4];
    const float* item_emb = (const float*)d_in[5];
    const float* cate_emb = (const float*)d_in[6];
    const float* mm_w     = (const float*)d_in[7];
    const float* mm_b     = (const float*)d_in[8];
    const float* ln_g     = (const float*)d_in[9];
    const float* ln_b     = (const float*)d_in[10];
    const float* gnn_W    = (const float*)d_in[11];
    const float* gnn_a    = (const float*)d_in[12];
    const float* se_w1    = (const float*)d_in[13];
    const float* se_b1    = (const float*)d_in[14];
    const float* se_w2    = (const float*)d_in[15];
    const float* se_b2    = (const float*)d_in[16];
    const float* bi_W     = (const float*)d_in[17];
    const float* w1       = (const float*)d_in[18];
    const float* b1       = (const float*)d_in[19];
    const float* bn1g     = (const float*)d_in[20];
    const float* bn1b     = (const float*)d_in[21];
    const float* w2       = (const float*)d_in[22];
    const float* b2       = (const float*)d_in[23];
    const float* bn2g     = (const float*)d_in[24];
    const float* bn2b     = (const float*)d_in[25];
    const float* w3       = (const float*)d_in[26];
    const float* b3       = (const float*)d_in[27];
    float* out = (float*)d_out;

    float *ps, *pv, *ph2;
    __nv_bfloat16 *pch, *pcl, *ph1h, *ph1l, *pw1h, *pw1l, *pw2h, *pw2l;
    cudaGetSymbolAddress((void**)&ps,   g_s);
    cudaGetSymbolAddress((void**)&pv,   g_vid);
    cudaGetSymbolAddress((void**)&ph2,  g_h2);
    cudaGetSymbolAddress((void**)&pch,  g_c_hi);
    cudaGetSymbolAddress((void**)&pcl,  g_c_lo);
    cudaGetSymbolAddress((void**)&ph1h, g_h1_hi);
    cudaGetSymbolAddress((void**)&ph1l, g_h1_lo);
    cudaGetSymbolAddress((void**)&pw1h, g_w1t_hi);
    cudaGetSymbolAddress((void**)&pw1l, g_w1t_lo);
    cudaGetSymbolAddress((void**)&pw2h, g_w2t_hi);
    cudaGetSymbolAddress((void**)&pw2l, g_w2t_lo);

    cudaFuncSetAttribute(k_mma, cudaFuncAttributeMaxDynamicSharedMemorySize, SMEM_MMA);

    // weight prep (bf16 split + transpose)
    k_wsplit<<<(CINn * H1N + 255) / 256, 256>>>(w1, pw1h, pw1l, CINn, H1N);
    k_wsplit<<<(H1N * H2N + 255) / 256, 256>>>(w2, pw2h, pw2l, H1N, H2N);

    k_features<<<Bn, 128>>>(item_id, item_mm, likes, views, item_seq,
                            item_emb, cate_emb, mm_w, mm_b, ln_g, ln_b);
    k_gnn<<<Bn, 128>>>(gnn_W, gnn_a, se_w1, se_b1, se_w2, se_b2);

    // bilinear: vid[b,f,:] = s[b,f,:] @ bi_W[f]
    {
        dim3 grid(Dn / BNg, Bn / BMg, 5);
        k_gemm<<<grid, 256>>>(ps, Fn * Dn, Dn, bi_W, Dn, (long)Dn * Dn,
                              pv, 5 * Dn, Dn, Dn);
    }
    k_pairs<<<Bn, 128>>>();

    // layer 1: c @ w1 (+bias,bn,gelu) -> h1 (bf16 hi/lo)
    {
        dim3 grid(H1N / BN, Bn / BM);
        k_mma<<<grid, 256, SMEM_MMA>>>(pch, pcl, pw1h, pw1l, CINn,
                                       nullptr, ph1h, ph1l, H1N,
                                       b1, bn1g, bn1b, 1);
    }
    // layer 2: h1 @ w2 (+bias,bn,gelu) -> h2 (fp32)
    {
        dim3 grid(H2N / BN, Bn / BM);
        k_mma<<<grid, 256, SMEM_MMA>>>(ph1h, ph1l, pw2h, pw2l, H1N,
                                       ph2, nullptr, nullptr, H2N,
                                       b2, bn2g, bn2b, 2);
    }
    k_final<<<Bn / 8, 256>>>(w3, b3, out);
}